// round 9
// baseline (speedup 1.0000x reference)
#include <cuda_runtime.h>
#include <cuda_bf16.h>
#include <cstdint>

// ============================================================================
// out = alpha*x + U * diag(g(lam)) * U^T * x       (Lambda diagonal)
// g(l) = sum_i 4*c_i/(a_i-b_i)^2 * relu((a_i-l)(l-b_i))
//
// Engine: mma.sync m16n8k16 bf16 (fp32 accum), hi/lo compensation
// (D += Ah*Bh + Ah*Bl + Al*Bh).  R9: split-K=4 -> 512 CTAs, 3 co-resident
// CTAs/SM (smem-capped) so sync/LDSM bubbles of one CTA overlap another's
// MMAs. fp32 partials merged by light kernels (deterministic).
// ============================================================================

#define NDIM 2048
#define FDIM 256
#define KDIM 2048
#define SPLITK 4
#define KSPLIT (KDIM / SPLITK)   // 512
#define BT   64            // CTA tile (M and N)
#define KT   64            // k-tile (64 bf16 = 128B row -> SW128 atoms)
#define NKT  (KSPLIT / KT) // 8 per split

#define STAGE_BYTES 32768  // Ah 8K | Al 8K | Bh 8K | Bl 8K
#define SMEM_DYN    (1024 + 2 * STAGE_BYTES)

// ------------------------- device scratch (no cudaMalloc) -------------------
__device__ __align__(16) __nv_bfloat16 g_Uhi [NDIM * NDIM];
__device__ __align__(16) __nv_bfloat16 g_Ulo [NDIM * NDIM];
__device__ __align__(16) __nv_bfloat16 g_Uthi[NDIM * NDIM];
__device__ __align__(16) __nv_bfloat16 g_Utlo[NDIM * NDIM];
__device__ __align__(16) __nv_bfloat16 g_Xthi[FDIM * NDIM];
__device__ __align__(16) __nv_bfloat16 g_Xtlo[FDIM * NDIM];
__device__ __align__(16) __nv_bfloat16 g_Wthi[FDIM * NDIM];
__device__ __align__(16) __nv_bfloat16 g_Wtlo[FDIM * NDIM];
__device__ __align__(16) float g_p[SPLITK][FDIM * NDIM];   // GEMM1 partials
__device__ __align__(16) float g_q[SPLITK][NDIM * FDIM];   // GEMM2 partials
__device__ float g_g[NDIM];

// ------------------------------- helpers ------------------------------------
__device__ __forceinline__ unsigned s2u(const void* p) {
    unsigned a;
    asm("{ .reg .u64 t; cvta.to.shared.u64 t, %1; cvt.u32.u64 %0, t; }" : "=r"(a) : "l"(p));
    return a;
}
__device__ __forceinline__ unsigned swz(unsigned o) { return o ^ ((o >> 3) & 0x70); }

__device__ __forceinline__ void cpa16(unsigned s, const void* g) {
    asm volatile("cp.async.cg.shared.global [%0], [%1], 16;" :: "r"(s), "l"(g));
}
__device__ __forceinline__ void ldm_x4(unsigned* r, unsigned addr) {
    asm volatile("ldmatrix.sync.aligned.m8n8.x4.shared.b16 {%0,%1,%2,%3}, [%4];"
                 : "=r"(r[0]), "=r"(r[1]), "=r"(r[2]), "=r"(r[3]) : "r"(addr));
}
__device__ __forceinline__ void mma16816(float* d, const unsigned* a, const unsigned* b) {
    asm volatile("mma.sync.aligned.m16n8k16.row.col.f32.bf16.bf16.f32 "
                 "{%0,%1,%2,%3}, {%4,%5,%6,%7}, {%8,%9}, {%0,%1,%2,%3};"
                 : "+f"(d[0]), "+f"(d[1]), "+f"(d[2]), "+f"(d[3])
                 : "r"(a[0]), "r"(a[1]), "r"(a[2]), "r"(a[3]), "r"(b[0]), "r"(b[1]));
}

// ------------------------------ prep kernels --------------------------------
__global__ void prep_g_k(const float* __restrict__ lam, const float* __restrict__ a,
                         const float* __restrict__ b, const float* __restrict__ c, int nf) {
    int j = blockIdx.x * blockDim.x + threadIdx.x;
    if (j >= NDIM) return;
    float lv = lam[(size_t)j * NDIM + j];
    float g = 0.f;
    for (int i = 0; i < nf; ++i) {
        float at = a[i], bt = b[i];
        float d = (at - lv) * (lv - bt);
        d = d > 0.f ? d : 0.f;
        float ab = at - bt;
        g += (4.f * c[i] / (ab * ab)) * d;
    }
    g_g[j] = g;
}

__global__ void prep_U_k(const float* __restrict__ U) {
    __shared__ float t[32][33];
    const int bx = blockIdx.x * 32, by = blockIdx.y * 32;
    const int tx = threadIdx.x, ty = threadIdx.y;
#pragma unroll
    for (int i = 0; i < 4; ++i) {
        int r = ty + i * 8;
        float v = U[(size_t)(by + r) * NDIM + bx + tx];
        t[r][tx] = v;
        __nv_bfloat16 h = __float2bfloat16(v);
        size_t o = (size_t)(by + r) * NDIM + bx + tx;
        g_Uhi[o] = h;
        g_Ulo[o] = __float2bfloat16(v - __bfloat162float(h));
    }
    __syncthreads();
#pragma unroll
    for (int i = 0; i < 4; ++i) {
        int r = ty + i * 8;
        float v = t[tx][r];                            // U[by+tx, bx+r]
        __nv_bfloat16 h = __float2bfloat16(v);
        size_t o = (size_t)(bx + r) * NDIM + by + tx;  // Ut[bx+r, by+tx]
        g_Uthi[o] = h;
        g_Utlo[o] = __float2bfloat16(v - __bfloat162float(h));
    }
}

__global__ void prep_X_k(const float* __restrict__ X) {
    __shared__ float t[32][33];
    const int bx = blockIdx.x * 32, by = blockIdx.y * 32;   // bx over F, by over N
    const int tx = threadIdx.x, ty = threadIdx.y;
#pragma unroll
    for (int i = 0; i < 4; ++i) {
        int r = ty + i * 8;
        t[r][tx] = X[(size_t)(by + r) * FDIM + bx + tx];
    }
    __syncthreads();
#pragma unroll
    for (int i = 0; i < 4; ++i) {
        int r = ty + i * 8;
        float v = t[tx][r];                            // X[by+tx, bx+r]
        __nv_bfloat16 h = __float2bfloat16(v);
        size_t o = (size_t)(bx + r) * NDIM + by + tx;  // Xt[bx+r, by+tx]
        g_Xthi[o] = h;
        g_Xtlo[o] = __float2bfloat16(v - __bfloat162float(h));
    }
}

// ------------------------------ merge kernels -------------------------------
// merge1: Wt = g[col] * sum_z p[z]  -> bf16 hi/lo      [FDIM x NDIM]
__global__ void merge1_k() {
    int i4 = (blockIdx.x * 256 + threadIdx.x) * 4;
    int col = i4 & (NDIM - 1);
    float4 p0 = *(const float4*)(g_p[0] + i4);
    float4 p1 = *(const float4*)(g_p[1] + i4);
    float4 p2 = *(const float4*)(g_p[2] + i4);
    float4 p3 = *(const float4*)(g_p[3] + i4);
    float4 gg = *(const float4*)(g_g + col);
    float v0 = ((p0.x + p1.x) + (p2.x + p3.x)) * gg.x;
    float v1 = ((p0.y + p1.y) + (p2.y + p3.y)) * gg.y;
    float v2 = ((p0.z + p1.z) + (p2.z + p3.z)) * gg.z;
    float v3 = ((p0.w + p1.w) + (p2.w + p3.w)) * gg.w;
    __nv_bfloat16 h0 = __float2bfloat16(v0), h1 = __float2bfloat16(v1);
    __nv_bfloat16 h2 = __float2bfloat16(v2), h3 = __float2bfloat16(v3);
    __nv_bfloat16 hv[4] = {h0, h1, h2, h3};
    __nv_bfloat16 lv[4] = {
        __float2bfloat16(v0 - __bfloat162float(h0)),
        __float2bfloat16(v1 - __bfloat162float(h1)),
        __float2bfloat16(v2 - __bfloat162float(h2)),
        __float2bfloat16(v3 - __bfloat162float(h3)) };
    *(uint2*)(g_Wthi + i4) = *(uint2*)hv;
    *(uint2*)(g_Wtlo + i4) = *(uint2*)lv;
}

// merge2: out = alpha*X + sum_z q[z]                   [NDIM x FDIM]
__global__ void merge2_k(const float* __restrict__ X,
                         const float* __restrict__ alpha, float* __restrict__ out) {
    int i4 = (blockIdx.x * 256 + threadIdx.x) * 4;
    const float av = alpha[0];
    float4 q0 = *(const float4*)(g_q[0] + i4);
    float4 q1 = *(const float4*)(g_q[1] + i4);
    float4 q2 = *(const float4*)(g_q[2] + i4);
    float4 q3 = *(const float4*)(g_q[3] + i4);
    float4 xv = *(const float4*)(X + i4);
    float4 o;
    o.x = av * xv.x + (q0.x + q1.x) + (q2.x + q3.x);
    o.y = av * xv.y + (q0.y + q1.y) + (q2.y + q3.y);
    o.z = av * xv.z + (q0.z + q1.z) + (q2.z + q3.z);
    o.w = av * xv.w + (q0.w + q1.w) + (q2.w + q3.w);
    *(float4*)(out + i4) = o;
}

// --------------------------- mma.sync GEMM kernel ---------------------------
// Partial C = A[m, ksplit] * B[n, ksplit]^T, fp32 partials to scratch.
// mode 0: A=Xt, B=Ut -> g_p[z];   mode 1: A=U, B=Wt -> g_q[z].
// 8 warps: warp_m in 0..3 (16 rows), warp_n in 0..1 (32 cols).
__global__ __launch_bounds__(256, 3)
void gemm_mma(int mode)
{
    extern __shared__ char smem_raw[];
    const unsigned sb = (s2u(smem_raw) + 1023u) & ~1023u;

    const int tid = threadIdx.x;
    const int wid = tid >> 5, lane = tid & 31;
    const int warp_m = wid >> 1, warp_n = wid & 1;
    const int m0 = blockIdx.x * BT, n0 = blockIdx.y * BT;
    const int kofs = blockIdx.z * KSPLIT;

    const __nv_bfloat16 *Ah, *Al, *Bh, *Bl;
    float* pout;
    int ldp;
    if (mode == 0) { Ah = g_Xthi; Al = g_Xtlo; Bh = g_Uthi; Bl = g_Utlo;
                     pout = g_p[blockIdx.z]; ldp = NDIM; }
    else           { Ah = g_Uhi;  Al = g_Ulo;  Bh = g_Wthi; Bl = g_Wtlo;
                     pout = g_q[blockIdx.z]; ldp = FDIM; }

    // -------- load plan: 8 cp.async x 16B per thread per stage --------
    const __nv_bfloat16* srcs[4] = {
        Ah + (size_t)m0 * KDIM + kofs, Al + (size_t)m0 * KDIM + kofs,
        Bh + (size_t)n0 * KDIM + kofs, Bl + (size_t)n0 * KDIM + kofs };
    unsigned soff[8], goff[8];
#pragma unroll
    for (int i = 0; i < 8; ++i) {
        int arr = i >> 1;
        int l = (i & 1) * 256 + tid;       // 0..511
        int row = l >> 3, c = l & 7;
        soff[i] = arr * 8192 + swz(row * 128 + c * 16);
        goff[i] = row * KDIM + c * 8;
    }

    auto load_tile = [&](int t, int stage) {
        const unsigned st = sb + stage * STAGE_BYTES;
        const unsigned kb = t * KT;
#pragma unroll
        for (int i = 0; i < 8; ++i)
            cpa16(st + soff[i], srcs[i >> 1] + goff[i] + kb);
        asm volatile("cp.async.commit_group;" ::: "memory");
    };

    // -------- ldmatrix address bases --------
    const unsigned abase =
        (warp_m * 16 + ((lane >> 3) & 1) * 8 + (lane & 7)) * 128 + (lane >> 4) * 16;
    unsigned bbase[2];
#pragma unroll
    for (int nf2 = 0; nf2 < 2; ++nf2) {
        int rowB = warp_n * 32 + nf2 * 16 + ((lane >> 4) & 1) * 8 + (lane & 7);
        bbase[nf2] = rowB * 128 + ((lane >> 3) & 1) * 16;
    }

    float acc[4][4] = {};

    load_tile(0, 0);
    for (int t = 0; t < NKT; ++t) {
        if (t + 1 < NKT) {
            load_tile(t + 1, (t + 1) & 1);
            asm volatile("cp.async.wait_group 1;" ::: "memory");
        } else {
            asm volatile("cp.async.wait_group 0;" ::: "memory");
        }
        __syncthreads();

        const unsigned stA = sb + (t & 1) * STAGE_BYTES;
        const unsigned stB = stA + 16384;
#pragma unroll
        for (int ks = 0; ks < 4; ++ks) {
            unsigned ah[4], al[4], bh[2][4], bl[2][4];
            ldm_x4(ah, stA + swz(abase + ks * 32));
            ldm_x4(al, stA + 8192 + swz(abase + ks * 32));
#pragma unroll
            for (int nf2 = 0; nf2 < 2; ++nf2) {
                ldm_x4(bh[nf2], stB + swz(bbase[nf2] + ks * 32));
                ldm_x4(bl[nf2], stB + 8192 + swz(bbase[nf2] + ks * 32));
            }
#pragma unroll
            for (int nf = 0; nf < 4; ++nf) {
                const unsigned* bhp = &bh[nf >> 1][(nf & 1) * 2];
                const unsigned* blp = &bl[nf >> 1][(nf & 1) * 2];
                mma16816(acc[nf], ah, bhp);
                mma16816(acc[nf], ah, blp);
                mma16816(acc[nf], al, bhp);
            }
        }
        __syncthreads();
    }

    // ---------------- epilogue: fp32 partials to scratch --------------------
    const int rbase = m0 + warp_m * 16 + (lane >> 2);
    const int cbase0 = n0 + warp_n * 32 + (lane & 3) * 2;
#pragma unroll
    for (int nf = 0; nf < 4; ++nf) {
        const int cb = cbase0 + nf * 8;
#pragma unroll
        for (int h = 0; h < 2; ++h) {
            const int row = rbase + h * 8;
            float2 v; v.x = acc[nf][h * 2 + 0]; v.y = acc[nf][h * 2 + 1];
            *(float2*)(pout + (size_t)row * ldp + cb) = v;
        }
    }
}

// ---------------------------------------------------------------------------
extern "C" void kernel_launch(void* const* d_in, const int* in_sizes, int n_in,
                              void* d_out, int out_size)
{
    const float* X     = (const float*)d_in[0];  // [N,F]
    const float* Lam   = (const float*)d_in[1];  // [N,N] diagonal
    const float* U     = (const float*)d_in[2];  // [N,N]
    const float* a     = (const float*)d_in[3];
    const float* b     = (const float*)d_in[4];
    const float* c     = (const float*)d_in[5];
    const float* alpha = (const float*)d_in[6];
    // d_in[7] = edge_index (unused by the reference math)
    const int nf = in_sizes[3];

    static bool attr_set = false;
    if (!attr_set) {
        cudaFuncSetAttribute(gemm_mma, cudaFuncAttributeMaxDynamicSharedMemorySize, SMEM_DYN);
        attr_set = true;
    }

    prep_g_k<<<NDIM / 256, 256>>>(Lam, a, b, c, nf);
    dim3 bt(32, 8);
    prep_X_k<<<dim3(FDIM / 32, NDIM / 32), bt>>>(X);
    prep_U_k<<<dim3(NDIM / 32, NDIM / 32), bt>>>(U);

    // GEMM1: M=FDIM x N=NDIM, split-K=4:  grid 4 x 32 x 4 = 512 CTAs
    gemm_mma<<<dim3(FDIM / BT, NDIM / BT, SPLITK), 256, SMEM_DYN>>>(0);
    merge1_k<<<(FDIM * NDIM / 4) / 256, 256>>>();
    // GEMM2: M=NDIM x N=FDIM, split-K=4:  grid 32 x 4 x 4 = 512 CTAs
    gemm_mma<<<dim3(NDIM / BT, FDIM / BT, SPLITK), 256, SMEM_DYN>>>(1);
    merge2_k<<<(NDIM * FDIM / 4) / 256, 256>>>(X, alpha, (float*)d_out);
}

// round 10
// speedup vs baseline: 1.0711x; 1.0711x over previous
#include <cuda_runtime.h>
#include <cuda_bf16.h>
#include <cstdint>

// ============================================================================
// out = alpha*x + U * diag(g(lam)) * U^T * x       (Lambda diagonal)
// g(l) = sum_i 4*c_i/(a_i-b_i)^2 * relu((a_i-l)(l-b_i))
//
// Engine: mma.sync m16n8k16 bf16 (fp32 accum), hi/lo compensation
// (D += Ah*Bh + Ah*Bl + Al*Bh).
// R10: smem-bandwidth fix — 32x32 warp tiles (CTA 128x64, 8 warps) raise
// fragment reuse from 256B/MMA to 170B/MMA (crossbar ceiling 50% -> 75%).
// split-K=4 retained (256 CTAs/GEMM, 2 co-resident CTAs/SM @ 97KB smem).
// ============================================================================

#define NDIM 2048
#define FDIM 256
#define KDIM 2048
#define SPLITK 4
#define KSPLIT (KDIM / SPLITK)   // 512
#define BM   128           // CTA tile M
#define BN   64            // CTA tile N
#define KT   64            // k-tile (64 bf16 = 128B row -> SW128 atoms)
#define NKT  (KSPLIT / KT) // 8 per split

// stage: AH 16K | AL 16K | BH 8K | BL 8K = 48K
#define OFF_AL 16384
#define OFF_BH 32768
#define OFF_BL 40960
#define STAGE_BYTES 49152
#define SMEM_DYN    (1024 + 2 * STAGE_BYTES)   // 99328

// ------------------------- device scratch (no cudaMalloc) -------------------
__device__ __align__(16) __nv_bfloat16 g_Uhi [NDIM * NDIM];
__device__ __align__(16) __nv_bfloat16 g_Ulo [NDIM * NDIM];
__device__ __align__(16) __nv_bfloat16 g_Uthi[NDIM * NDIM];
__device__ __align__(16) __nv_bfloat16 g_Utlo[NDIM * NDIM];
__device__ __align__(16) __nv_bfloat16 g_Xthi[FDIM * NDIM];
__device__ __align__(16) __nv_bfloat16 g_Xtlo[FDIM * NDIM];
__device__ __align__(16) __nv_bfloat16 g_Wthi[FDIM * NDIM];
__device__ __align__(16) __nv_bfloat16 g_Wtlo[FDIM * NDIM];
__device__ __align__(16) float g_p[SPLITK][FDIM * NDIM];   // GEMM1 partials
__device__ __align__(16) float g_q[SPLITK][NDIM * FDIM];   // GEMM2 partials
__device__ float g_g[NDIM];

// ------------------------------- helpers ------------------------------------
__device__ __forceinline__ unsigned s2u(const void* p) {
    unsigned a;
    asm("{ .reg .u64 t; cvta.to.shared.u64 t, %1; cvt.u32.u64 %0, t; }" : "=r"(a) : "l"(p));
    return a;
}
__device__ __forceinline__ unsigned swz(unsigned o) { return o ^ ((o >> 3) & 0x70); }

__device__ __forceinline__ void cpa16(unsigned s, const void* g) {
    asm volatile("cp.async.cg.shared.global [%0], [%1], 16;" :: "r"(s), "l"(g));
}
__device__ __forceinline__ void ldm_x4(unsigned* r, unsigned addr) {
    asm volatile("ldmatrix.sync.aligned.m8n8.x4.shared.b16 {%0,%1,%2,%3}, [%4];"
                 : "=r"(r[0]), "=r"(r[1]), "=r"(r[2]), "=r"(r[3]) : "r"(addr));
}
__device__ __forceinline__ void mma16816(float* d, const unsigned* a, const unsigned* b) {
    asm volatile("mma.sync.aligned.m16n8k16.row.col.f32.bf16.bf16.f32 "
                 "{%0,%1,%2,%3}, {%4,%5,%6,%7}, {%8,%9}, {%0,%1,%2,%3};"
                 : "+f"(d[0]), "+f"(d[1]), "+f"(d[2]), "+f"(d[3])
                 : "r"(a[0]), "r"(a[1]), "r"(a[2]), "r"(a[3]), "r"(b[0]), "r"(b[1]));
}

// ------------------------------ prep kernels --------------------------------
__global__ void prep_g_k(const float* __restrict__ lam, const float* __restrict__ a,
                         const float* __restrict__ b, const float* __restrict__ c, int nf) {
    int j = blockIdx.x * blockDim.x + threadIdx.x;
    if (j >= NDIM) return;
    float lv = lam[(size_t)j * NDIM + j];
    float g = 0.f;
    for (int i = 0; i < nf; ++i) {
        float at = a[i], bt = b[i];
        float d = (at - lv) * (lv - bt);
        d = d > 0.f ? d : 0.f;
        float ab = at - bt;
        g += (4.f * c[i] / (ab * ab)) * d;
    }
    g_g[j] = g;
}

__global__ void prep_U_k(const float* __restrict__ U) {
    __shared__ float t[32][33];
    const int bx = blockIdx.x * 32, by = blockIdx.y * 32;
    const int tx = threadIdx.x, ty = threadIdx.y;
#pragma unroll
    for (int i = 0; i < 4; ++i) {
        int r = ty + i * 8;
        float v = U[(size_t)(by + r) * NDIM + bx + tx];
        t[r][tx] = v;
        __nv_bfloat16 h = __float2bfloat16(v);
        size_t o = (size_t)(by + r) * NDIM + bx + tx;
        g_Uhi[o] = h;
        g_Ulo[o] = __float2bfloat16(v - __bfloat162float(h));
    }
    __syncthreads();
#pragma unroll
    for (int i = 0; i < 4; ++i) {
        int r = ty + i * 8;
        float v = t[tx][r];                            // U[by+tx, bx+r]
        __nv_bfloat16 h = __float2bfloat16(v);
        size_t o = (size_t)(bx + r) * NDIM + by + tx;  // Ut[bx+r, by+tx]
        g_Uthi[o] = h;
        g_Utlo[o] = __float2bfloat16(v - __bfloat162float(h));
    }
}

__global__ void prep_X_k(const float* __restrict__ X) {
    __shared__ float t[32][33];
    const int bx = blockIdx.x * 32, by = blockIdx.y * 32;   // bx over F, by over N
    const int tx = threadIdx.x, ty = threadIdx.y;
#pragma unroll
    for (int i = 0; i < 4; ++i) {
        int r = ty + i * 8;
        t[r][tx] = X[(size_t)(by + r) * FDIM + bx + tx];
    }
    __syncthreads();
#pragma unroll
    for (int i = 0; i < 4; ++i) {
        int r = ty + i * 8;
        float v = t[tx][r];                            // X[by+tx, bx+r]
        __nv_bfloat16 h = __float2bfloat16(v);
        size_t o = (size_t)(bx + r) * NDIM + by + tx;  // Xt[bx+r, by+tx]
        g_Xthi[o] = h;
        g_Xtlo[o] = __float2bfloat16(v - __bfloat162float(h));
    }
}

// ------------------------------ merge kernels -------------------------------
__global__ void merge1_k() {
    int i4 = (blockIdx.x * 256 + threadIdx.x) * 4;
    int col = i4 & (NDIM - 1);
    float4 p0 = *(const float4*)(g_p[0] + i4);
    float4 p1 = *(const float4*)(g_p[1] + i4);
    float4 p2 = *(const float4*)(g_p[2] + i4);
    float4 p3 = *(const float4*)(g_p[3] + i4);
    float4 gg = *(const float4*)(g_g + col);
    float v0 = ((p0.x + p1.x) + (p2.x + p3.x)) * gg.x;
    float v1 = ((p0.y + p1.y) + (p2.y + p3.y)) * gg.y;
    float v2 = ((p0.z + p1.z) + (p2.z + p3.z)) * gg.z;
    float v3 = ((p0.w + p1.w) + (p2.w + p3.w)) * gg.w;
    __nv_bfloat16 h0 = __float2bfloat16(v0), h1 = __float2bfloat16(v1);
    __nv_bfloat16 h2 = __float2bfloat16(v2), h3 = __float2bfloat16(v3);
    __nv_bfloat16 hv[4] = {h0, h1, h2, h3};
    __nv_bfloat16 lv[4] = {
        __float2bfloat16(v0 - __bfloat162float(h0)),
        __float2bfloat16(v1 - __bfloat162float(h1)),
        __float2bfloat16(v2 - __bfloat162float(h2)),
        __float2bfloat16(v3 - __bfloat162float(h3)) };
    *(uint2*)(g_Wthi + i4) = *(uint2*)hv;
    *(uint2*)(g_Wtlo + i4) = *(uint2*)lv;
}

__global__ void merge2_k(const float* __restrict__ X,
                         const float* __restrict__ alpha, float* __restrict__ out) {
    int i4 = (blockIdx.x * 256 + threadIdx.x) * 4;
    const float av = alpha[0];
    float4 q0 = *(const float4*)(g_q[0] + i4);
    float4 q1 = *(const float4*)(g_q[1] + i4);
    float4 q2 = *(const float4*)(g_q[2] + i4);
    float4 q3 = *(const float4*)(g_q[3] + i4);
    float4 xv = *(const float4*)(X + i4);
    float4 o;
    o.x = av * xv.x + (q0.x + q1.x) + (q2.x + q3.x);
    o.y = av * xv.y + (q0.y + q1.y) + (q2.y + q3.y);
    o.z = av * xv.z + (q0.z + q1.z) + (q2.z + q3.z);
    o.w = av * xv.w + (q0.w + q1.w) + (q2.w + q3.w);
    *(float4*)(out + i4) = o;
}

// --------------------------- mma.sync GEMM kernel ---------------------------
// Partial C[BM x BN] = A[m, ksplit] * B[n, ksplit]^T -> fp32 scratch.
// mode 0: A=Xt (M=FDIM), B=Ut -> g_p[z];  mode 1: A=U (M=NDIM), B=Wt -> g_q[z].
// 8 warps as 4(m) x 2(n): warp tile 32x32.
__global__ __launch_bounds__(256, 2)
void gemm_mma(int mode)
{
    extern __shared__ char smem_raw[];
    const unsigned sb = (s2u(smem_raw) + 1023u) & ~1023u;

    const int tid = threadIdx.x;
    const int wid = tid >> 5, lane = tid & 31;
    const int warp_m = wid >> 1, warp_n = wid & 1;   // 4 x 2
    const int m0 = blockIdx.x * BM, n0 = blockIdx.y * BN;
    const int kofs = blockIdx.z * KSPLIT;

    const __nv_bfloat16 *Ah, *Al, *Bh, *Bl;
    float* pout;
    int ldp;
    if (mode == 0) { Ah = g_Xthi; Al = g_Xtlo; Bh = g_Uthi; Bl = g_Utlo;
                     pout = g_p[blockIdx.z]; ldp = NDIM; }
    else           { Ah = g_Uhi;  Al = g_Ulo;  Bh = g_Wthi; Bl = g_Wtlo;
                     pout = g_q[blockIdx.z]; ldp = FDIM; }

    // -------- load plan: 12 cp.async x 16B per thread per stage (48KB) ------
    // flat chunk idx l in [0,3072): [0,1024)=AH, [1024,2048)=AL,
    //                               [2048,2560)=BH, [2560,3072)=BL
    const __nv_bfloat16* baseA_h = Ah + (size_t)m0 * KDIM + kofs;
    const __nv_bfloat16* baseA_l = Al + (size_t)m0 * KDIM + kofs;
    const __nv_bfloat16* baseB_h = Bh + (size_t)n0 * KDIM + kofs;
    const __nv_bfloat16* baseB_l = Bl + (size_t)n0 * KDIM + kofs;
    const __nv_bfloat16* srcp[12];
    unsigned soff[12], goff[12];
#pragma unroll
    for (int i = 0; i < 12; ++i) {
        int l = i * 256 + tid;
        int region, lr;
        if (l < 1024)      { region = 0; lr = l; }
        else if (l < 2048) { region = 1; lr = l - 1024; }
        else if (l < 2560) { region = 2; lr = l - 2048; }
        else               { region = 3; lr = l - 2560; }
        int row = lr >> 3, c = lr & 7;
        static const unsigned rofs_c[4] = {0u, OFF_AL, OFF_BH, OFF_BL};
        soff[i] = rofs_c[region] + swz(row * 128 + c * 16);
        goff[i] = row * KDIM + c * 8;
        srcp[i] = (region == 0) ? baseA_h : (region == 1) ? baseA_l
                : (region == 2) ? baseB_h : baseB_l;
    }

    auto load_tile = [&](int t, int stage) {
        const unsigned st = sb + stage * STAGE_BYTES;
        const unsigned kb = t * KT;
#pragma unroll
        for (int i = 0; i < 12; ++i)
            cpa16(st + soff[i], srcp[i] + goff[i] + kb);
        asm volatile("cp.async.commit_group;" ::: "memory");
    };

    // -------- ldmatrix address bases --------
    unsigned abase[2], bbase[2];
#pragma unroll
    for (int mf = 0; mf < 2; ++mf) {
        int rowA = warp_m * 32 + mf * 16 + ((lane >> 3) & 1) * 8 + (lane & 7);
        abase[mf] = rowA * 128 + (lane >> 4) * 16;
    }
#pragma unroll
    for (int nf2 = 0; nf2 < 2; ++nf2) {
        int rowB = warp_n * 32 + nf2 * 16 + ((lane >> 4) & 1) * 8 + (lane & 7);
        bbase[nf2] = rowB * 128 + ((lane >> 3) & 1) * 16;
    }

    float acc[2][4][4] = {};

    load_tile(0, 0);
    for (int t = 0; t < NKT; ++t) {
        if (t + 1 < NKT) {
            load_tile(t + 1, (t + 1) & 1);
            asm volatile("cp.async.wait_group 1;" ::: "memory");
        } else {
            asm volatile("cp.async.wait_group 0;" ::: "memory");
        }
        __syncthreads();

        const unsigned stA = sb + (t & 1) * STAGE_BYTES;
        const unsigned stB = stA + OFF_BH;
#pragma unroll
        for (int ks = 0; ks < 4; ++ks) {
            unsigned ah[2][4], al[2][4], bh[2][4], bl[2][4];
#pragma unroll
            for (int mf = 0; mf < 2; ++mf) {
                ldm_x4(ah[mf], stA + swz(abase[mf] + ks * 32));
                ldm_x4(al[mf], stA + OFF_AL + swz(abase[mf] + ks * 32));
            }
#pragma unroll
            for (int nf2 = 0; nf2 < 2; ++nf2) {
                ldm_x4(bh[nf2], stB + swz(bbase[nf2] + ks * 32));
                ldm_x4(bl[nf2], stB + (OFF_BL - OFF_BH) + swz(bbase[nf2] + ks * 32));
            }
#pragma unroll
            for (int mf = 0; mf < 2; ++mf) {
                // wave 1: hh (4 independent)
#pragma unroll
                for (int nf = 0; nf < 4; ++nf)
                    mma16816(acc[mf][nf], ah[mf], &bh[nf >> 1][(nf & 1) * 2]);
                // wave 2: hl
#pragma unroll
                for (int nf = 0; nf < 4; ++nf)
                    mma16816(acc[mf][nf], ah[mf], &bl[nf >> 1][(nf & 1) * 2]);
                // wave 3: lh
#pragma unroll
                for (int nf = 0; nf < 4; ++nf)
                    mma16816(acc[mf][nf], al[mf], &bh[nf >> 1][(nf & 1) * 2]);
            }
        }
        __syncthreads();
    }

    // ---------------- epilogue: fp32 partials to scratch --------------------
    const int rbase = m0 + warp_m * 32 + (lane >> 2);
    const int cbase0 = n0 + warp_n * 32 + (lane & 3) * 2;
#pragma unroll
    for (int mf = 0; mf < 2; ++mf)
#pragma unroll
        for (int nf = 0; nf < 4; ++nf) {
            const int cb = cbase0 + nf * 8;
#pragma unroll
            for (int h = 0; h < 2; ++h) {
                const int row = rbase + mf * 16 + h * 8;
                float2 v;
                v.x = acc[mf][nf][h * 2 + 0];
                v.y = acc[mf][nf][h * 2 + 1];
                *(float2*)(pout + (size_t)row * ldp + cb) = v;
            }
        }
}

// ---------------------------------------------------------------------------
extern "C" void kernel_launch(void* const* d_in, const int* in_sizes, int n_in,
                              void* d_out, int out_size)
{
    const float* X     = (const float*)d_in[0];  // [N,F]
    const float* Lam   = (const float*)d_in[1];  // [N,N] diagonal
    const float* U     = (const float*)d_in[2];  // [N,N]
    const float* a     = (const float*)d_in[3];
    const float* b     = (const float*)d_in[4];
    const float* c     = (const float*)d_in[5];
    const float* alpha = (const float*)d_in[6];
    // d_in[7] = edge_index (unused by the reference math)
    const int nf = in_sizes[3];

    static bool attr_set = false;
    if (!attr_set) {
        cudaFuncSetAttribute(gemm_mma, cudaFuncAttributeMaxDynamicSharedMemorySize, SMEM_DYN);
        attr_set = true;
    }

    prep_g_k<<<NDIM / 256, 256>>>(Lam, a, b, c, nf);
    dim3 bt(32, 8);
    prep_X_k<<<dim3(FDIM / 32, NDIM / 32), bt>>>(X);
    prep_U_k<<<dim3(NDIM / 32, NDIM / 32), bt>>>(U);

    // GEMM1: M=FDIM x N=NDIM, split-K=4:  grid 2 x 32 x 4 = 256 CTAs
    gemm_mma<<<dim3(FDIM / BM, NDIM / BN, SPLITK), 256, SMEM_DYN>>>(0);
    merge1_k<<<(FDIM * NDIM / 4) / 256, 256>>>();
    // GEMM2: M=NDIM x N=FDIM, split-K=4:  grid 16 x 4 x 4 = 256 CTAs
    gemm_mma<<<dim3(NDIM / BM, FDIM / BN, SPLITK), 256, SMEM_DYN>>>(1);
    merge2_k<<<(NDIM * FDIM / 4) / 256, 256>>>(X, alpha, (float*)d_out);
}